// round 5
// baseline (speedup 1.0000x reference)
#include <cuda_runtime.h>
#include <cuda_fp16.h>
#include <math.h>

// Problem constants
#define B_TOTAL 512
#define T_STEPS 1024
#define F_IN    32
#define HID     128
#define BC      4                 // batch rows per block
#define NBLK    (B_TOTAL / BC)    // 128 blocks
#define NTHR    128               // 4 warps: 1 per SMSP; each thread owns column j for all 4 rows
#define P1K     48                // layer1 k-rows staged in smem (rest streamed from L2)

// Packed fp16 weights, k-major, gate-interleaved: idx = k*512 + 4*j + gate
__device__ __half g_W0h[160 * 512];  // layer0: k in [0,32)=Wih0, [32,160)=Whh0
__device__ __half g_W1h[256 * 512];  // layer1: k in [0,128)=Wih1, [128,256)=Whh1
__device__ float  g_B0[512];         // bih0+bhh0, gate-interleaved
__device__ float  g_B1[512];

__global__ void pack_kernel(const float* __restrict__ Wih0, const float* __restrict__ Whh0,
                            const float* __restrict__ bih0, const float* __restrict__ bhh0,
                            const float* __restrict__ Wih1, const float* __restrict__ Whh1,
                            const float* __restrict__ bih1, const float* __restrict__ bhh1)
{
    int idx = blockIdx.x * blockDim.x + threadIdx.x;
    if (idx < 160 * 512) {
        int k = idx >> 9, c = idx & 511;
        int j = c >> 2, g = c & 3, row = g * HID + j;
        float w = (k < F_IN) ? Wih0[row * F_IN + k] : Whh0[row * HID + (k - F_IN)];
        g_W0h[idx] = __float2half_rn(w);
    }
    if (idx < 256 * 512) {
        int k = idx >> 9, c = idx & 511;
        int j = c >> 2, g = c & 3, row = g * HID + j;
        float w = (k < HID) ? Wih1[row * HID + k] : Whh1[row * HID + (k - HID)];
        g_W1h[idx] = __float2half_rn(w);
    }
    if (idx < 512) {
        int j = idx >> 2, g = idx & 3, row = g * HID + j;
        g_B0[idx] = bih0[row] + bhh0[row];
        g_B1[idx] = bih1[row] + bhh1[row];
    }
}

// ---- packed f32x2 helpers ----
__device__ __forceinline__ unsigned long long pk2(float lo, float hi) {
    unsigned long long r;
    asm("mov.b64 %0, {%1, %2};" : "=l"(r) : "r"(__float_as_uint(lo)), "r"(__float_as_uint(hi)));
    return r;
}
__device__ __forceinline__ void upk2(unsigned long long v, float& lo, float& hi) {
    unsigned int a, b;
    asm("mov.b64 {%0, %1}, %2;" : "=r"(a), "=r"(b) : "l"(v));
    lo = __uint_as_float(a); hi = __uint_as_float(b);
}
__device__ __forceinline__ void fma2(unsigned long long& d, unsigned long long a, unsigned long long b) {
    asm("fma.rn.f32x2 %0, %1, %2, %0;" : "+l"(d) : "l"(a), "l"(b));
}

__device__ __forceinline__ float sigf(float x) {
    return 1.0f / (1.0f + __expf(-x));
}
__device__ __forceinline__ float tanhfast(float x) {
    float cx = fminf(fmaxf(x, -15.f), 15.f);
    float e  = __expf(-2.f * cx);
    return (1.f - e) / (1.f + e);
}

// processes one k-value's weights (4 gates, fp16x4 in wv) against 4 rows' acts
__device__ __forceinline__ void mac4(uint2 wv, const float* aq,
                                     unsigned long long* accif, unsigned long long* accgo)
{
    float2 wif = __half22float2(*reinterpret_cast<const __half2*>(&wv.x));
    float2 wgo = __half22float2(*reinterpret_cast<const __half2*>(&wv.y));
    unsigned long long wifp = pk2(wif.x, wif.y);
    unsigned long long wgop = pk2(wgo.x, wgo.y);
    #pragma unroll
    for (int r = 0; r < 4; ++r) {
        unsigned long long ap = pk2(aq[r], aq[r]);
        fma2(accif[r], wifp, ap);
        fma2(accgo[r], wgop, ap);
    }
}

__global__ __launch_bounds__(NTHR, 1)
void lstm_main(const float* __restrict__ x,
               const float* __restrict__ ln_g, const float* __restrict__ ln_b,
               const float* __restrict__ W1,   const float* __restrict__ b1,
               const float* __restrict__ W2,   const float* __restrict__ b2,
               float* __restrict__ out)
{
    extern __shared__ char dsm[];          // [0,163840) = W0 fp16, [163840,212992) = W1[0:48k] fp16
    __shared__ float a0[BC][160];          // [0:32) = x_t, [32:160) = h0 state
    __shared__ float a1[BC][256];          // [0:128) = h0_new (layer1 input), [128:256) = h1 state
    __shared__ float red[BC][64];
    __shared__ float mv[BC][2];

    const int bid = blockIdx.x;
    const int tid = threadIdx.x;
    const int j   = tid;                   // hidden column, 0..127

    // ---- one-time: stage weights into smem ----
    {
        const uint4* s0 = reinterpret_cast<const uint4*>(g_W0h);
        uint4* d0 = reinterpret_cast<uint4*>(dsm);
        for (int i = tid; i < 160 * 512 * 2 / 16; i += NTHR) d0[i] = s0[i];
        const uint4* s1 = reinterpret_cast<const uint4*>(g_W1h);
        uint4* d1 = reinterpret_cast<uint4*>(dsm + 160 * 512 * 2);
        for (int i = tid; i < P1K * 512 * 2 / 16; i += NTHR) d1[i] = s1[i];
    }
    for (int i = tid; i < BC * 160; i += NTHR) (&a0[0][0])[i] = 0.f;
    for (int i = tid; i < BC * 256; i += NTHR) (&a1[0][0])[i] = 0.f;

    const uint2* __restrict__ W0s = reinterpret_cast<const uint2*>(dsm);
    const uint2* __restrict__ W1s = reinterpret_cast<const uint2*>(dsm + 160 * 512 * 2);
    const uint2* __restrict__ W1g = reinterpret_cast<const uint2*>(g_W1h);
    const float4 b0v = reinterpret_cast<const float4*>(g_B0)[j];
    const float4 b1v = reinterpret_cast<const float4*>(g_B1)[j];

    float c0[BC] = {0.f, 0.f, 0.f, 0.f};
    float c1[BC] = {0.f, 0.f, 0.f, 0.f};

    const float* xbase = x + (size_t)(bid * BC) * T_STEPS * F_IN;
    const int xr = tid >> 5, xk = tid & 31;            // x staging map (128 = 4x32)
    const float* xsrc = xbase + (size_t)xr * T_STEPS * F_IN + xk;

    __syncthreads();   // weights + zeroed state visible

    for (int t = 0; t < T_STEPS; ++t) {
        // stage x_t (this barrier also publishes last step's h1 writes)
        a0[xr][xk] = xsrc[t * F_IN];
        __syncthreads();

        // ---------------- layer 0: gates = [x_t, h0] @ W0 (all smem) ----------------
        unsigned long long accif[BC] = {0, 0, 0, 0};
        unsigned long long accgo[BC] = {0, 0, 0, 0};
        #pragma unroll 2
        for (int k4 = 0; k4 < 40; ++k4) {
            float4 av[BC];
            #pragma unroll
            for (int r = 0; r < BC; ++r) av[r] = *reinterpret_cast<const float4*>(&a0[r][k4 * 4]);
            #pragma unroll
            for (int q = 0; q < 4; ++q) {
                uint2 wv = W0s[(k4 * 4 + q) * 128 + j];
                float aq[BC] = {(&av[0].x)[q], (&av[1].x)[q], (&av[2].x)[q], (&av[3].x)[q]};
                mac4(wv, aq, accif, accgo);
            }
        }
        // prefetch first global layer1 weight group (no dependency on acts)
        uint2 buf[4];
        #pragma unroll
        for (int q = 0; q < 4; ++q) buf[q] = W1g[(P1K + q) * 128 + j];

        __syncthreads();   // all reads of a0 h-region done before overwrite
        #pragma unroll
        for (int r = 0; r < BC; ++r) {
            float gi, gf, gg, go;
            upk2(accif[r], gi, gf); upk2(accgo[r], gg, go);
            float ig = sigf(gi + b0v.x), fg = sigf(gf + b0v.y);
            float gv = tanhfast(gg + b0v.z), og = sigf(go + b0v.w);
            c0[r] = fg * c0[r] + ig * gv;
            float h = og * tanhfast(c0[r]);
            a0[r][32 + j] = h;  a1[r][j] = h;
        }
        __syncthreads();   // publish h0_new before layer1 reads a1

        // ---------------- layer 1: gates = [h0_new, h1] @ W1 ----------------
        #pragma unroll
        for (int r = 0; r < BC; ++r) { accif[r] = 0; accgo[r] = 0; }
        // smem portion: k in [0, P1K)
        #pragma unroll 2
        for (int k4 = 0; k4 < P1K / 4; ++k4) {
            float4 av[BC];
            #pragma unroll
            for (int r = 0; r < BC; ++r) av[r] = *reinterpret_cast<const float4*>(&a1[r][k4 * 4]);
            #pragma unroll
            for (int q = 0; q < 4; ++q) {
                uint2 wv = W1s[(k4 * 4 + q) * 128 + j];
                float aq[BC] = {(&av[0].x)[q], (&av[1].x)[q], (&av[2].x)[q], (&av[3].x)[q]};
                mac4(wv, aq, accif, accgo);
            }
        }
        // global portion: k in [P1K, 256), software-pipelined
        for (int k4 = P1K / 4; k4 < 64; ++k4) {
            uint2 nbuf[4];
            int nk = (k4 + 1 < 64) ? (k4 + 1) * 4 : 252;
            #pragma unroll
            for (int q = 0; q < 4; ++q) nbuf[q] = W1g[(nk + q) * 128 + j];
            float4 av[BC];
            #pragma unroll
            for (int r = 0; r < BC; ++r) av[r] = *reinterpret_cast<const float4*>(&a1[r][k4 * 4]);
            #pragma unroll
            for (int q = 0; q < 4; ++q) {
                float aq[BC] = {(&av[0].x)[q], (&av[1].x)[q], (&av[2].x)[q], (&av[3].x)[q]};
                mac4(buf[q], aq, accif, accgo);
            }
            #pragma unroll
            for (int q = 0; q < 4; ++q) buf[q] = nbuf[q];
        }
        __syncthreads();   // all reads of a1 h1-region done before overwrite
        #pragma unroll
        for (int r = 0; r < BC; ++r) {
            float gi, gf, gg, go;
            upk2(accif[r], gi, gf); upk2(accgo[r], gg, go);
            float ig = sigf(gi + b1v.x), fg = sigf(gf + b1v.y);
            float gv = tanhfast(gg + b1v.z), og = sigf(go + b1v.w);
            c1[r] = fg * c1[r] + ig * gv;
            a1[r][128 + j] = og * tanhfast(c1[r]);
        }
        // next iteration's staging __syncthreads publishes h1
    }
    __syncthreads();

    // ---------------- head: LayerNorm -> Linear(64) -> ReLU -> Linear(1) -> sigmoid ----
    if (tid < BC) {
        int r = tid;
        float s = 0.f;
        for (int k = 0; k < HID; ++k) s += a1[r][128 + k];
        float mu = s * (1.f / HID);
        float v = 0.f;
        for (int k = 0; k < HID; ++k) { float d = a1[r][128 + k] - mu; v += d * d; }
        v *= (1.f / HID);
        mv[r][0] = mu;
        mv[r][1] = rsqrtf(v + 1e-5f);
    }
    __syncthreads();
    #pragma unroll
    for (int it = 0; it < 2; ++it) {
        int idx = tid + it * NTHR;          // 0..255
        int r = idx >> 6, u = idx & 63;
        float mu = mv[r][0], rs = mv[r][1];
        float acc = b1[u];
        for (int k = 0; k < HID; ++k) {
            float lnv = (a1[r][128 + k] - mu) * rs * ln_g[k] + ln_b[k];
            acc += lnv * W1[u * HID + k];
        }
        red[r][u] = fmaxf(acc, 0.f);
    }
    __syncthreads();
    if (tid < BC) {
        int r = tid;
        float y = b2[0];
        for (int u = 0; u < 64; ++u) y += red[r][u] * W2[u];
        out[bid * BC + r] = sigf(y);
    }
}

extern "C" void kernel_launch(void* const* d_in, const int* in_sizes, int n_in,
                              void* d_out, int out_size)
{
    const float* x    = (const float*)d_in[0];
    const float* Wih0 = (const float*)d_in[1];
    const float* Whh0 = (const float*)d_in[2];
    const float* bih0 = (const float*)d_in[3];
    const float* bhh0 = (const float*)d_in[4];
    const float* Wih1 = (const float*)d_in[5];
    const float* Whh1 = (const float*)d_in[6];
    const float* bih1 = (const float*)d_in[7];
    const float* bhh1 = (const float*)d_in[8];
    const float* ln_g = (const float*)d_in[9];
    const float* ln_b = (const float*)d_in[10];
    const float* W1   = (const float*)d_in[11];
    const float* b1   = (const float*)d_in[12];
    const float* W2   = (const float*)d_in[13];
    const float* b2   = (const float*)d_in[14];
    float* out = (float*)d_out;

    const int dyn_smem = 160 * 512 * 2 + P1K * 512 * 2;   // 212992 bytes
    cudaFuncSetAttribute(lstm_main, cudaFuncAttributeMaxDynamicSharedMemorySize, dyn_smem);

    pack_kernel<<<512, 256>>>(Wih0, Whh0, bih0, bhh0, Wih1, Whh1, bih1, bhh1);
    lstm_main<<<NBLK, NTHR, dyn_smem>>>(x, ln_g, ln_b, W1, b1, W2, b2, out);
}